// round 16
// baseline (speedup 1.0000x reference)
#include <cuda_runtime.h>
#include <cuda_fp16.h>
#include <math.h>
#include <stdint.h>

#define Bb 8
#define Nn 4096
#define Cc 512
#define Hh 8
#define DHd 64
#define Tt (Bb*Nn)   // 32768 tokens
#define NSPLIT 16

// Scratch (allocation-free rule: device globals)
__device__ __half g_xn[Tt*Cc];                // LayerNorm output [T,C], fp16
__device__ __half g_qkv[3*Bb*Hh*DHd*Nn];      // [i][b][h][d][n], fp16
__device__ __half g_y[Tt*Cc];                 // gelu(attn@v) [T,C], fp16
__device__ float  g_Sp[64*NSPLIT*64*64];      // partial raw S (fp32)
__device__ float  g_ss[2*64*NSPLIT*64];       // partial sum-of-squares (fp32)
__device__ __half g_attn[64*64*64];           // softmaxed attn [bh][d][e], fp16
__device__ __half g_wq[1536*512];             // fp16 qkv_w
__device__ __half g_wp[512*512];              // fp16 proj_w

__device__ __forceinline__ uint32_t smem_u32(const void* p) {
    uint32_t a;
    asm("{ .reg .u64 t; cvta.to.shared.u64 t, %1; cvt.u32.u64 %0, t; }"
        : "=r"(a) : "l"(p));
    return a;
}
__device__ __forceinline__ void cp16(uint32_t daddr, const void* src) {
    asm volatile("{ .reg .u64 p; cvta.to.global.u64 p, %1;"
                 "  cp.async.cg.shared.global [%0], [p], 16; }"
                 :: "r"(daddr), "l"(src) : "memory");
}
#define LDM_X4(a0,a1,a2,a3,addr) \
    asm volatile("ldmatrix.sync.aligned.m8n8.x4.shared.b16 {%0,%1,%2,%3}, [%4];" \
        : "=r"(a0), "=r"(a1), "=r"(a2), "=r"(a3) : "r"(addr))
#define LDM_X2(b0,b1,addr) \
    asm volatile("ldmatrix.sync.aligned.m8n8.x2.shared.b16 {%0,%1}, [%2];" \
        : "=r"(b0), "=r"(b1) : "r"(addr))
#define LDM_X2_T(b0,b1,addr) \
    asm volatile("ldmatrix.sync.aligned.m8n8.x2.trans.shared.b16 {%0,%1}, [%2];" \
        : "=r"(b0), "=r"(b1) : "r"(addr))
#define MMA_F16(c0,c1,c2,c3,a0,a1,a2,a3,b0,b1) \
    asm volatile("mma.sync.aligned.m16n8k16.row.col.f32.f16.f16.f32 " \
        "{%0,%1,%2,%3}, {%4,%5,%6,%7}, {%8,%9}, {%0,%1,%2,%3};" \
        : "+f"(c0), "+f"(c1), "+f"(c2), "+f"(c3) \
        : "r"(a0), "r"(a1), "r"(a2), "r"(a3), "r"(b0), "r"(b1))

// ===========================================================================
// K1: fused LayerNorm (blocks 0..32767) + weight fp16 conversion (rest)
// ===========================================================================
__global__ void ln_round_kernel(const float* __restrict__ x,
                                const float* __restrict__ gam,
                                const float* __restrict__ bet,
                                const float* __restrict__ qkv_w,
                                const float* __restrict__ proj_w) {
    const int tid = threadIdx.x;           // 128
    if (blockIdx.x < Tt) {
        const int t = blockIdx.x;
        const float4 xv = *(const float4*)(x + (size_t)t*Cc + tid*4);
        float s  = xv.x + xv.y + xv.z + xv.w;
        float ss = xv.x*xv.x + xv.y*xv.y + xv.z*xv.z + xv.w*xv.w;
        #pragma unroll
        for (int o = 16; o > 0; o >>= 1) {
            s  += __shfl_xor_sync(0xffffffffu, s,  o);
            ss += __shfl_xor_sync(0xffffffffu, ss, o);
        }
        __shared__ float shs[4], shss[4];
        const int w = tid >> 5, l = tid & 31;
        if (l == 0) { shs[w] = s; shss[w] = ss; }
        __syncthreads();
        const float tot  = shs[0]  + shs[1]  + shs[2]  + shs[3];
        const float tots = shss[0] + shss[1] + shss[2] + shss[3];
        const float mean = tot * (1.0f/512.0f);
        const float var  = tots * (1.0f/512.0f) - mean*mean;
        const float inv  = rsqrtf(var + 1e-5f);
        const float4 gv = *(const float4*)(gam + tid*4);
        const float4 bv = *(const float4*)(bet + tid*4);
        __half2 p0 = __floats2half2_rn((xv.x - mean)*inv*gv.x + bv.x,
                                       (xv.y - mean)*inv*gv.y + bv.y);
        __half2 p1 = __floats2half2_rn((xv.z - mean)*inv*gv.z + bv.z,
                                       (xv.w - mean)*inv*gv.w + bv.w);
        __half* dst = g_xn + (size_t)t*Cc + tid*4;
        *(__half2*)dst = p0;
        *(__half2*)(dst + 2) = p1;
    } else {
        // weight conversion: 2048 extra blocks x 128 thr, 1 float4 each iter
        const int n1 = 1536*512/4, n2 = 512*512/4;   // 196608 + 65536 = 262144 tasks
        const int base = (blockIdx.x - Tt)*128 + tid;
        for (int i = base; i < n1 + n2; i += 2048*128) {
            const float4 v = (i < n1) ? ((const float4*)qkv_w)[i]
                                      : ((const float4*)proj_w)[i - n1];
            __half2 p0 = __floats2half2_rn(v.x, v.y);
            __half2 p1 = __floats2half2_rn(v.z, v.w);
            __half* dst = (i < n1) ? (g_wq + (size_t)i*4) : (g_wp + (size_t)(i - n1)*4);
            *(__half2*)dst = p0;
            *(__half2*)(dst + 2) = p1;
        }
    }
}

// ===========================================================================
// fp16 mma.sync GEMM: C[t,o] = sum_c A[t,c]*W[o,c].
// Block 128(m) x 128(n), 256 thr (8 warps, 2m x 4n), warp tile 64x32.
// LDKH=40 halves/row, k-chunk 32, cp.async 4-stage, mma m16n8k16.
// launch_bounds(256,2): 2 CTAs/SM (smem 2x80KB=160KB, regs ~110 < 128 cap).
// ===========================================================================
#define LDKH 40
#define A_BYTES (128*LDKH*2)     // 10240
#define W_BYTES (128*LDKH*2)     // 10240
#define BUF_BYTES (A_BYTES + W_BYTES)  // 20480
#define NSTAGE 4
#define GEMM_SMEM (NSTAGE*BUF_BYTES)   // 81920

template<int EPI>
__global__ void __launch_bounds__(256, 2) mmagemm(const float* __restrict__ bias,
                                                  float* __restrict__ out) {
    extern __shared__ char smem[];
    const uint32_t sb = smem_u32(smem);
    const __half* __restrict__ A = (EPI == 0) ? g_xn : g_y;
    const __half* __restrict__ W = (EPI == 0) ? g_wq : g_wp;
    const int tid = threadIdx.x;
    const int wid = tid >> 5, lane = tid & 31;
    const int t0 = blockIdx.y * 128;
    const int o0 = blockIdx.x * 128;
    const int wm = wid >> 2, wn = wid & 3;   // 2 x 4 warp grid
    const int g = lane >> 2, tg = lane & 3;

    // staging mapping (16B = 8 halves per task): A 512 tasks, W 512 tasks
    int ra[2], ca[2];
    #pragma unroll
    for (int j = 0; j < 2; j++) { const int idx = j*256 + tid; ra[j] = idx >> 2; ca[j] = (idx & 3)*8; }

    const uint32_t baseA = sb + (uint32_t)(((wm*64 + (lane & 15))*LDKH + ((lane & 16) ? 8 : 0)) * 2);
    const uint32_t baseB = sb + A_BYTES + (uint32_t)(((wn*32 + (lane & 7))*LDKH + ((lane & 8) ? 8 : 0)) * 2);

    float acc[4][4][4];
    #pragma unroll
    for (int mt = 0; mt < 4; mt++)
        #pragma unroll
        for (int nt = 0; nt < 4; nt++)
            #pragma unroll
            for (int r = 0; r < 4; r++) acc[mt][nt][r] = 0.0f;

    #pragma unroll
    for (int s = 0; s < 3; s++) {
        const uint32_t sA = sb + s*BUF_BYTES, sW = sA + A_BYTES;
        const int k0 = s * 32;
        #pragma unroll
        for (int j = 0; j < 2; j++) {
            cp16(sA + (ra[j]*LDKH + ca[j])*2, A + (size_t)(t0 + ra[j])*512 + k0 + ca[j]);
            cp16(sW + (ra[j]*LDKH + ca[j])*2, W + (size_t)(o0 + ra[j])*512 + k0 + ca[j]);
        }
        asm volatile("cp.async.commit_group;" ::: "memory");
    }

    for (int c = 0; c < 16; c++) {
        // stage c must be complete; outstanding groups = stages c..min(c+2,15)
        if (c <= 13)      asm volatile("cp.async.wait_group 2;" ::: "memory");
        else if (c == 14) asm volatile("cp.async.wait_group 1;" ::: "memory");
        else              asm volatile("cp.async.wait_group 0;" ::: "memory");
        __syncthreads();
        if (c + 3 < 16) {
            const int k0 = (c + 3) * 32;
            const uint32_t sA = sb + ((c + 3) % NSTAGE)*BUF_BYTES;
            const uint32_t sW = sA + A_BYTES;
            #pragma unroll
            for (int j = 0; j < 2; j++) {
                cp16(sA + (ra[j]*LDKH + ca[j])*2, A + (size_t)(t0 + ra[j])*512 + k0 + ca[j]);
                cp16(sW + (ra[j]*LDKH + ca[j])*2, W + (size_t)(o0 + ra[j])*512 + k0 + ca[j]);
            }
            asm volatile("cp.async.commit_group;" ::: "memory");
        }
        const uint32_t aoff = baseA + (c % NSTAGE)*BUF_BYTES;
        const uint32_t boff = baseB + (c % NSTAGE)*BUF_BYTES;
        #pragma unroll
        for (int ks = 0; ks < 2; ks++) {
            uint32_t a[4][4], b[4][2];
            #pragma unroll
            for (int mt = 0; mt < 4; mt++)
                LDM_X4(a[mt][0], a[mt][1], a[mt][2], a[mt][3],
                       aoff + (uint32_t)((mt*16*LDKH + ks*16) * 2));
            #pragma unroll
            for (int nt = 0; nt < 4; nt++)
                LDM_X2(b[nt][0], b[nt][1], boff + (uint32_t)((nt*8*LDKH + ks*16) * 2));
            #pragma unroll
            for (int mt = 0; mt < 4; mt++)
                #pragma unroll
                for (int nt = 0; nt < 4; nt++)
                    MMA_F16(acc[mt][nt][0], acc[mt][nt][1], acc[mt][nt][2], acc[mt][nt][3],
                            a[mt][0], a[mt][1], a[mt][2], a[mt][3], b[nt][0], b[nt][1]);
        }
    }

    const int m0g = t0 + wm*64;
    const int o0g = o0 + wn*32;
    if (EPI == 0) {
        const int i_ = o0g >> 9;
        const int h  = (o0g >> 6) & 7;
        const int b  = m0g >> 12;
        const int rowbase = ((i_*8 + b)*8 + h)*64 + (o0g & 63);
        #pragma unroll
        for (int mt = 0; mt < 4; mt++) {
            const int t1 = m0g + mt*16 + g;
            const int n1 = t1 & 4095;
            #pragma unroll
            for (int nt = 0; nt < 4; nt++) {
                const int row = rowbase + nt*8 + tg*2;
                g_qkv[(size_t)row*4096 + n1]            = __float2half(acc[mt][nt][0]);
                g_qkv[(size_t)(row + 1)*4096 + n1]      = __float2half(acc[mt][nt][1]);
                g_qkv[(size_t)row*4096 + n1 + 8]        = __float2half(acc[mt][nt][2]);
                g_qkv[(size_t)(row + 1)*4096 + n1 + 8]  = __float2half(acc[mt][nt][3]);
            }
        }
    } else {
        #pragma unroll
        for (int mt = 0; mt < 4; mt++) {
            const int t1 = m0g + mt*16 + g;
            #pragma unroll
            for (int nt = 0; nt < 4; nt++) {
                const int o = o0g + nt*8 + tg*2;
                const float b0 = bias[o], b1 = bias[o + 1];
                float2 v0; v0.x = acc[mt][nt][0] + b0; v0.y = acc[mt][nt][1] + b1;
                float2 v1; v1.x = acc[mt][nt][2] + b0; v1.y = acc[mt][nt][3] + b1;
                *(float2*)(out + (size_t)t1*512 + o)       = v0;
                *(float2*)(out + (size_t)(t1 + 8)*512 + o) = v1;
            }
        }
    }
}

// ===========================================================================
// K4a: fp16 mma S-partials: per (bh, split) a 64x64x256 GEMM. 128 thr.
// ===========================================================================
#define QLDKH 40
__global__ void __launch_bounds__(128) attn_qk_mma() {
    __shared__ __half qs[64*QLDKH];
    __shared__ __half ks_[64*QLDKH];
    const int bh = blockIdx.x;
    const int split = blockIdx.y;
    const __half* __restrict__ q = g_qkv + (size_t)bh * 64 * 4096;
    const __half* __restrict__ k = g_qkv + (size_t)(64 + bh) * 64 * 4096;
    const int tid = threadIdx.x;
    const int wid = tid >> 5, lane = tid & 31;
    const uint32_t sq = smem_u32(qs), sk = smem_u32(ks_);
    const int r0 = tid >> 2;
    const int c8 = (tid & 3) * 8;

    const uint32_t aoff = sq + (uint32_t)(((wid*16 + (lane & 15))*QLDKH + ((lane & 16) ? 8 : 0)) * 2);
    const uint32_t boff = sk + (uint32_t)(((lane & 7)*QLDKH + ((lane & 8) ? 8 : 0)) * 2);

    float acc[8][4];
    #pragma unroll
    for (int nt = 0; nt < 8; nt++)
        #pragma unroll
        for (int r = 0; r < 4; r++) acc[nt][r] = 0.0f;
    float ssq[2] = {0,0}, ssk[2] = {0,0};

    for (int ch = 0; ch < 8; ch++) {
        const int n0 = split*256 + ch*32;
        #pragma unroll
        for (int j = 0; j < 2; j++) {
            const int row = j*32 + r0;
            const float4 qv = *(const float4*)(q + (size_t)row*4096 + n0 + c8);
            *(float4*)&qs[row*QLDKH + c8] = qv;
            const __half2* qh = (const __half2*)&qv;
            #pragma unroll
            for (int p = 0; p < 4; p++) {
                const float2 f = __half22float2(qh[p]);
                ssq[j] += f.x*f.x + f.y*f.y;
            }
            const float4 kv = *(const float4*)(k + (size_t)row*4096 + n0 + c8);
            *(float4*)&ks_[row*QLDKH + c8] = kv;
            const __half2* kh = (const __half2*)&kv;
            #pragma unroll
            for (int p = 0; p < 4; p++) {
                const float2 f = __half22float2(kh[p]);
                ssk[j] += f.x*f.x + f.y*f.y;
            }
        }
        __syncthreads();
        #pragma unroll
        for (int ks = 0; ks < 2; ks++) {
            uint32_t a[4], b[8][2];
            LDM_X4(a[0], a[1], a[2], a[3], aoff + (uint32_t)((ks*16) * 2));
            #pragma unroll
            for (int nt = 0; nt < 8; nt++)
                LDM_X2(b[nt][0], b[nt][1], boff + (uint32_t)((nt*8*QLDKH + ks*16) * 2));
            #pragma unroll
            for (int nt = 0; nt < 8; nt++)
                MMA_F16(acc[nt][0], acc[nt][1], acc[nt][2], acc[nt][3],
                        a[0], a[1], a[2], a[3], b[nt][0], b[nt][1]);
        }
        __syncthreads();
    }
    #pragma unroll
    for (int o = 1; o < 4; o <<= 1) {
        #pragma unroll
        for (int j = 0; j < 2; j++) {
            ssq[j] += __shfl_xor_sync(0xffffffffu, ssq[j], o);
            ssk[j] += __shfl_xor_sync(0xffffffffu, ssk[j], o);
        }
    }
    if ((tid & 3) == 0) {
        #pragma unroll
        for (int j = 0; j < 2; j++) {
            const int row = j*32 + r0;
            g_ss[((size_t)bh*NSPLIT + split)*64 + row]        = ssq[j];
            g_ss[((size_t)(64 + bh)*NSPLIT + split)*64 + row] = ssk[j];
        }
    }
    float* dst = g_Sp + ((size_t)(bh*NSPLIT + split)) * 4096;
    const int g = lane >> 2, tg = lane & 3;
    const int d0 = wid*16 + g;
    #pragma unroll
    for (int nt = 0; nt < 8; nt++) {
        const int e = nt*8 + tg*2;
        float2 v0; v0.x = acc[nt][0]; v0.y = acc[nt][1];
        float2 v1; v1.x = acc[nt][2]; v1.y = acc[nt][3];
        *(float2*)(dst + d0*64 + e)       = v0;
        *(float2*)(dst + (d0 + 8)*64 + e) = v1;
    }
}

// ===========================================================================
// K4b: reduce NSPLIT partials, apply norm scales * temperature, softmax over e.
// ===========================================================================
#define PAD 65
__global__ void __launch_bounds__(256) softmax_kernel(const float* __restrict__ temperature) {
    __shared__ float S[64*PAD];
    __shared__ float scq[64], sck[64];
    const int bh = blockIdx.x;
    const int tid = threadIdx.x;
    for (int idx = tid; idx < 4096; idx += 256) {
        float s = 0.0f;
        #pragma unroll
        for (int sp = 0; sp < NSPLIT; sp++)
            s += g_Sp[((size_t)(bh*NSPLIT + sp))*4096 + idx];
        S[(idx >> 6)*PAD + (idx & 63)] = s;
    }
    if (tid < 128) {
        const int iq = tid >> 6;
        const int r = tid & 63;
        float s = 0.0f;
        #pragma unroll
        for (int sp = 0; sp < NSPLIT; sp++)
            s += g_ss[((size_t)(iq*64 + bh)*NSPLIT + sp)*64 + r];
        const float nrm = fmaxf(sqrtf(s), 1e-12f);
        if (iq == 0) scq[r] = temperature[bh & 7] / nrm;
        else         sck[r] = 1.0f / nrm;
    }
    __syncthreads();
    if (tid < 64) {
        const int d = tid;
        const float qsc = scq[d];
        float mx = -1e30f;
        #pragma unroll 8
        for (int e = 0; e < 64; e++) {
            const float v = S[d*PAD + e] * qsc * sck[e];
            S[d*PAD + e] = v;
            mx = fmaxf(mx, v);
        }
        float sm = 0.0f;
        #pragma unroll 8
        for (int e = 0; e < 64; e++) {
            const float ex = __expf(S[d*PAD + e] - mx);
            S[d*PAD + e] = ex;
            sm += ex;
        }
        const float inv = 1.0f / sm;
        #pragma unroll 8
        for (int e = 0; e < 64; e++)
            g_attn[(size_t)bh*4096 + d*64 + e] = __float2half(S[d*PAD + e] * inv);
    }
}

// ===========================================================================
// K4c: fp16 mma attn@v + GELU.
// ===========================================================================
#define ALD 72     // As row stride (halves): attn [d][e]
#define VLD 136    // Vs row stride (halves): v [e][n]
__global__ void __launch_bounds__(256) attn_v_mma() {
    __shared__ __half As[64*ALD];
    __shared__ __half Vs[64*VLD];
    const int bh = blockIdx.x;
    const int b = bh >> 3, h = bh & 7;
    const int n0 = blockIdx.y * 128;
    const __half* __restrict__ v = g_qkv + (size_t)(128 + bh) * 64 * 4096;
    const int tid = threadIdx.x;
    const int wid = tid >> 5, lane = tid & 31;
    const int wm = wid >> 1, wn = wid & 1;
    const uint32_t sa = smem_u32(As), sv = smem_u32(Vs);

    #pragma unroll
    for (int j = 0; j < 2; j++) {
        const int idx = j*256 + tid;
        const int d = idx >> 3;
        const int e8 = (idx & 7) * 8;
        cp16(sa + (d*ALD + e8)*2, g_attn + (size_t)bh*4096 + d*64 + e8);
    }
    #pragma unroll
    for (int j = 0; j < 4; j++) {
        const int idx = j*256 + tid;
        const int e = idx >> 4;
        const int n8 = (idx & 15) * 8;
        cp16(sv + (e*VLD + n8)*2, v + (size_t)e*4096 + n0 + n8);
    }
    asm volatile("cp.async.commit_group;" ::: "memory");
    asm volatile("cp.async.wait_group 0;" ::: "memory");
    __syncthreads();

    const uint32_t aoff = sa + (uint32_t)(((wm*16 + (lane & 15))*ALD + ((lane & 16) ? 8 : 0)) * 2);
    const uint32_t boff = sv + (uint32_t)(((lane & 15)*VLD + wn*64) * 2);

    float acc[8][4];
    #pragma unroll
    for (int nt = 0; nt < 8; nt++)
        #pragma unroll
        for (int r = 0; r < 4; r++) acc[nt][r] = 0.0f;

    #pragma unroll
    for (int ks = 0; ks < 4; ks++) {
        uint32_t a[4], bfr[8][2];
        LDM_X4(a[0], a[1], a[2], a[3], aoff + (uint32_t)((ks*16) * 2));
        #pragma unroll
        for (int nt = 0; nt < 8; nt++)
            LDM_X2_T(bfr[nt][0], bfr[nt][1],
                     boff + (uint32_t)((ks*16*VLD + nt*8) * 2));
        #pragma unroll
        for (int nt = 0; nt < 8; nt++)
            MMA_F16(acc[nt][0], acc[nt][1], acc[nt][2], acc[nt][3],
                    a[0], a[1], a[2], a[3], bfr[nt][0], bfr[nt][1]);
    }

    const int g = lane >> 2, tg = lane & 3;
    const int d0 = wm*16 + g;
    #pragma unroll
    for (int nt = 0; nt < 8; nt++) {
        const int n = n0 + wn*64 + nt*8 + tg*2;
        const size_t t0r = (size_t)b*4096 + n;
        #pragma unroll
        for (int r = 0; r < 4; r++) {
            const int d = d0 + (r >> 1)*8;
            const size_t t = t0r + (r & 1);
            const float xg = acc[nt][r];
            g_y[t*512 + h*64 + d] =
                __float2half(0.5f*xg*(1.0f + erff(xg*0.70710678118654752f)));
        }
    }
}

// ===========================================================================
extern "C" void kernel_launch(void* const* d_in, const int* in_sizes, int n_in,
                              void* d_out, int out_size) {
    const float* x           = (const float*)d_in[0];
    const float* ln_g        = (const float*)d_in[1];
    const float* ln_b        = (const float*)d_in[2];
    const float* qkv_w       = (const float*)d_in[3];
    const float* temperature = (const float*)d_in[4];
    const float* proj_w      = (const float*)d_in[5];
    const float* proj_b      = (const float*)d_in[6];
    float* out = (float*)d_out;

    cudaFuncSetAttribute(mmagemm<0>, cudaFuncAttributeMaxDynamicSharedMemorySize, GEMM_SMEM);
    cudaFuncSetAttribute(mmagemm<1>, cudaFuncAttributeMaxDynamicSharedMemorySize, GEMM_SMEM);

    ln_round_kernel<<<Tt + 2048, 128>>>(x, ln_g, ln_b, qkv_w, proj_w);
    mmagemm<0><<<dim3(1536/128, Tt/128), 256, GEMM_SMEM>>>(nullptr, nullptr);
    attn_qk_mma<<<dim3(64, NSPLIT), 128>>>();
    softmax_kernel<<<64, 256>>>(temperature);
    attn_v_mma<<<dim3(64, 32), 256>>>();
    mmagemm<1><<<dim3(512/128, Tt/128), 256, GEMM_SMEM>>>(proj_b, out);
}

// round 17
// speedup vs baseline: 1.1262x; 1.1262x over previous
#include <cuda_runtime.h>
#include <cuda_fp16.h>
#include <math.h>
#include <stdint.h>

#define Bb 8
#define Nn 4096
#define Cc 512
#define Hh 8
#define DHd 64
#define Tt (Bb*Nn)   // 32768 tokens
#define NSPLIT 16

// Scratch (allocation-free rule: device globals)
__device__ __half g_xn[Tt*Cc];                // LayerNorm output [T,C], fp16
__device__ __half g_qkv[3*Bb*Hh*DHd*Nn];      // [i][b][h][d][n], fp16
__device__ __half g_y[Tt*Cc];                 // gelu(attn@v) [T,C], fp16
__device__ float  g_Sp[64*NSPLIT*64*64];      // partial raw S (fp32)
__device__ float  g_ss[2*64*NSPLIT*64];       // partial sum-of-squares (fp32)
__device__ __half g_attn[64*64*64];           // softmaxed attn [bh][d][e], fp16
__device__ __half g_wq[1536*512];             // fp16 qkv_w
__device__ __half g_wp[512*512];              // fp16 proj_w

__device__ __forceinline__ uint32_t smem_u32(const void* p) {
    uint32_t a;
    asm("{ .reg .u64 t; cvta.to.shared.u64 t, %1; cvt.u32.u64 %0, t; }"
        : "=r"(a) : "l"(p));
    return a;
}
__device__ __forceinline__ void cp16(uint32_t daddr, const void* src) {
    asm volatile("{ .reg .u64 p; cvta.to.global.u64 p, %1;"
                 "  cp.async.cg.shared.global [%0], [p], 16; }"
                 :: "r"(daddr), "l"(src) : "memory");
}
#define LDM_X4(a0,a1,a2,a3,addr) \
    asm volatile("ldmatrix.sync.aligned.m8n8.x4.shared.b16 {%0,%1,%2,%3}, [%4];" \
        : "=r"(a0), "=r"(a1), "=r"(a2), "=r"(a3) : "r"(addr))
#define LDM_X2(b0,b1,addr) \
    asm volatile("ldmatrix.sync.aligned.m8n8.x2.shared.b16 {%0,%1}, [%2];" \
        : "=r"(b0), "=r"(b1) : "r"(addr))
#define LDM_X2_T(b0,b1,addr) \
    asm volatile("ldmatrix.sync.aligned.m8n8.x2.trans.shared.b16 {%0,%1}, [%2];" \
        : "=r"(b0), "=r"(b1) : "r"(addr))
#define MMA_F16(c0,c1,c2,c3,a0,a1,a2,a3,b0,b1) \
    asm volatile("mma.sync.aligned.m16n8k16.row.col.f32.f16.f16.f32 " \
        "{%0,%1,%2,%3}, {%4,%5,%6,%7}, {%8,%9}, {%0,%1,%2,%3};" \
        : "+f"(c0), "+f"(c1), "+f"(c2), "+f"(c3) \
        : "r"(a0), "r"(a1), "r"(a2), "r"(a3), "r"(b0), "r"(b1))

// ===========================================================================
// K0: convert weights to fp16
// ===========================================================================
__global__ void round_w_kernel(const float* __restrict__ qkv_w,
                               const float* __restrict__ proj_w) {
    const int n1 = 1536*512/4, n2 = 512*512/4;
    for (int i = blockIdx.x*blockDim.x + threadIdx.x; i < n1 + n2;
         i += gridDim.x*blockDim.x) {
        const float4 v = (i < n1) ? ((const float4*)qkv_w)[i]
                                  : ((const float4*)proj_w)[i - n1];
        __half2 p0 = __floats2half2_rn(v.x, v.y);
        __half2 p1 = __floats2half2_rn(v.z, v.w);
        __half* dst = (i < n1) ? (g_wq + (size_t)i*4) : (g_wp + (size_t)(i - n1)*4);
        *(__half2*)dst = p0;
        *(__half2*)(dst + 2) = p1;
    }
}

// ===========================================================================
// K1: LayerNorm (outputs fp16)
// ===========================================================================
__global__ void ln_kernel(const float* __restrict__ x,
                          const float* __restrict__ gam,
                          const float* __restrict__ bet) {
    const int t = blockIdx.x;
    const int tid = threadIdx.x;           // 128
    const float4 xv = *(const float4*)(x + (size_t)t*Cc + tid*4);
    float s  = xv.x + xv.y + xv.z + xv.w;
    float ss = xv.x*xv.x + xv.y*xv.y + xv.z*xv.z + xv.w*xv.w;
    #pragma unroll
    for (int o = 16; o > 0; o >>= 1) {
        s  += __shfl_xor_sync(0xffffffffu, s,  o);
        ss += __shfl_xor_sync(0xffffffffu, ss, o);
    }
    __shared__ float shs[4], shss[4];
    const int w = tid >> 5, l = tid & 31;
    if (l == 0) { shs[w] = s; shss[w] = ss; }
    __syncthreads();
    const float tot  = shs[0]  + shs[1]  + shs[2]  + shs[3];
    const float tots = shss[0] + shss[1] + shss[2] + shss[3];
    const float mean = tot * (1.0f/512.0f);
    const float var  = tots * (1.0f/512.0f) - mean*mean;
    const float inv  = rsqrtf(var + 1e-5f);
    const float4 gv = *(const float4*)(gam + tid*4);
    const float4 bv = *(const float4*)(bet + tid*4);
    __half2 p0 = __floats2half2_rn((xv.x - mean)*inv*gv.x + bv.x,
                                   (xv.y - mean)*inv*gv.y + bv.y);
    __half2 p1 = __floats2half2_rn((xv.z - mean)*inv*gv.z + bv.z,
                                   (xv.w - mean)*inv*gv.w + bv.w);
    __half* dst = g_xn + (size_t)t*Cc + tid*4;
    *(__half2*)dst = p0;
    *(__half2*)(dst + 2) = p1;
}

// ===========================================================================
// fp16 mma.sync GEMM (R15 exact): 128x128 block, 256 thr, 3-stage, 2 CTAs/SM.
// ===========================================================================
#define LDKH 40
#define A_BYTES (128*LDKH*2)     // 10240
#define W_BYTES (128*LDKH*2)     // 10240
#define BUF_BYTES (A_BYTES + W_BYTES)  // 20480
#define GEMM_SMEM (3*BUF_BYTES)        // 61440

template<int EPI>
__global__ void __launch_bounds__(256, 2) mmagemm(const float* __restrict__ bias,
                                                  float* __restrict__ out) {
    extern __shared__ char smem[];
    const uint32_t sb = smem_u32(smem);
    const __half* __restrict__ A = (EPI == 0) ? g_xn : g_y;
    const __half* __restrict__ W = (EPI == 0) ? g_wq : g_wp;
    const int tid = threadIdx.x;
    const int wid = tid >> 5, lane = tid & 31;
    const int t0 = blockIdx.y * 128;
    const int o0 = blockIdx.x * 128;
    const int wm = wid >> 2, wn = wid & 3;   // 2 x 4 warp grid
    const int g = lane >> 2, tg = lane & 3;

    int ra[2], ca[2];
    #pragma unroll
    for (int j = 0; j < 2; j++) { const int idx = j*256 + tid; ra[j] = idx >> 2; ca[j] = (idx & 3)*8; }

    const uint32_t baseA = sb + (uint32_t)(((wm*64 + (lane & 15))*LDKH + ((lane & 16) ? 8 : 0)) * 2);
    const uint32_t baseB = sb + A_BYTES + (uint32_t)(((wn*32 + (lane & 7))*LDKH + ((lane & 8) ? 8 : 0)) * 2);

    float acc[4][4][4];
    #pragma unroll
    for (int mt = 0; mt < 4; mt++)
        #pragma unroll
        for (int nt = 0; nt < 4; nt++)
            #pragma unroll
            for (int r = 0; r < 4; r++) acc[mt][nt][r] = 0.0f;

    #pragma unroll
    for (int s = 0; s < 2; s++) {
        const uint32_t sA = sb + s*BUF_BYTES, sW = sA + A_BYTES;
        const int k0 = s * 32;
        #pragma unroll
        for (int j = 0; j < 2; j++) {
            cp16(sA + (ra[j]*LDKH + ca[j])*2, A + (size_t)(t0 + ra[j])*512 + k0 + ca[j]);
            cp16(sW + (ra[j]*LDKH + ca[j])*2, W + (size_t)(o0 + ra[j])*512 + k0 + ca[j]);
        }
        asm volatile("cp.async.commit_group;" ::: "memory");
    }

    for (int c = 0; c < 16; c++) {
        if (c < 15) asm volatile("cp.async.wait_group 1;" ::: "memory");
        else        asm volatile("cp.async.wait_group 0;" ::: "memory");
        __syncthreads();
        if (c + 2 < 16) {
            const int k0 = (c + 2) * 32;
            const uint32_t sA = sb + ((c + 2) % 3)*BUF_BYTES;
            const uint32_t sW = sA + A_BYTES;
            #pragma unroll
            for (int j = 0; j < 2; j++) {
                cp16(sA + (ra[j]*LDKH + ca[j])*2, A + (size_t)(t0 + ra[j])*512 + k0 + ca[j]);
                cp16(sW + (ra[j]*LDKH + ca[j])*2, W + (size_t)(o0 + ra[j])*512 + k0 + ca[j]);
            }
            asm volatile("cp.async.commit_group;" ::: "memory");
        }
        const uint32_t aoff = baseA + (c % 3)*BUF_BYTES;
        const uint32_t boff = baseB + (c % 3)*BUF_BYTES;
        #pragma unroll
        for (int ks = 0; ks < 2; ks++) {
            uint32_t a[4][4], b[4][2];
            #pragma unroll
            for (int mt = 0; mt < 4; mt++)
                LDM_X4(a[mt][0], a[mt][1], a[mt][2], a[mt][3],
                       aoff + (uint32_t)((mt*16*LDKH + ks*16) * 2));
            #pragma unroll
            for (int nt = 0; nt < 4; nt++)
                LDM_X2(b[nt][0], b[nt][1], boff + (uint32_t)((nt*8*LDKH + ks*16) * 2));
            #pragma unroll
            for (int mt = 0; mt < 4; mt++)
                #pragma unroll
                for (int nt = 0; nt < 4; nt++)
                    MMA_F16(acc[mt][nt][0], acc[mt][nt][1], acc[mt][nt][2], acc[mt][nt][3],
                            a[mt][0], a[mt][1], a[mt][2], a[mt][3], b[nt][0], b[nt][1]);
        }
    }

    const int m0g = t0 + wm*64;
    const int o0g = o0 + wn*32;
    if (EPI == 0) {
        const int i_ = o0g >> 9;
        const int h  = (o0g >> 6) & 7;
        const int b  = m0g >> 12;
        const int rowbase = ((i_*8 + b)*8 + h)*64 + (o0g & 63);
        #pragma unroll
        for (int mt = 0; mt < 4; mt++) {
            const int t1 = m0g + mt*16 + g;
            const int n1 = t1 & 4095;
            #pragma unroll
            for (int nt = 0; nt < 4; nt++) {
                const int row = rowbase + nt*8 + tg*2;
                g_qkv[(size_t)row*4096 + n1]            = __float2half(acc[mt][nt][0]);
                g_qkv[(size_t)(row + 1)*4096 + n1]      = __float2half(acc[mt][nt][1]);
                g_qkv[(size_t)row*4096 + n1 + 8]        = __float2half(acc[mt][nt][2]);
                g_qkv[(size_t)(row + 1)*4096 + n1 + 8]  = __float2half(acc[mt][nt][3]);
            }
        }
    } else {
        #pragma unroll
        for (int mt = 0; mt < 4; mt++) {
            const int t1 = m0g + mt*16 + g;
            #pragma unroll
            for (int nt = 0; nt < 4; nt++) {
                const int o = o0g + nt*8 + tg*2;
                const float b0 = bias[o], b1 = bias[o + 1];
                float2 v0; v0.x = acc[mt][nt][0] + b0; v0.y = acc[mt][nt][1] + b1;
                float2 v1; v1.x = acc[mt][nt][2] + b0; v1.y = acc[mt][nt][3] + b1;
                *(float2*)(out + (size_t)t1*512 + o)       = v0;
                *(float2*)(out + (size_t)(t1 + 8)*512 + o) = v1;
            }
        }
    }
}

// ===========================================================================
// K4a: fp16 mma S-partials: per (bh, split) a 64x64x256 GEMM. 128 thr.
// ===========================================================================
#define QLDKH 40
__global__ void __launch_bounds__(128) attn_qk_mma() {
    __shared__ __half qs[64*QLDKH];
    __shared__ __half ks_[64*QLDKH];
    const int bh = blockIdx.x;
    const int split = blockIdx.y;
    const __half* __restrict__ q = g_qkv + (size_t)bh * 64 * 4096;
    const __half* __restrict__ k = g_qkv + (size_t)(64 + bh) * 64 * 4096;
    const int tid = threadIdx.x;
    const int wid = tid >> 5, lane = tid & 31;
    const uint32_t sq = smem_u32(qs), sk = smem_u32(ks_);
    const int r0 = tid >> 2;
    const int c8 = (tid & 3) * 8;

    const uint32_t aoff = sq + (uint32_t)(((wid*16 + (lane & 15))*QLDKH + ((lane & 16) ? 8 : 0)) * 2);
    const uint32_t boff = sk + (uint32_t)(((lane & 7)*QLDKH + ((lane & 8) ? 8 : 0)) * 2);

    float acc[8][4];
    #pragma unroll
    for (int nt = 0; nt < 8; nt++)
        #pragma unroll
        for (int r = 0; r < 4; r++) acc[nt][r] = 0.0f;
    float ssq[2] = {0,0}, ssk[2] = {0,0};

    for (int ch = 0; ch < 8; ch++) {
        const int n0 = split*256 + ch*32;
        #pragma unroll
        for (int j = 0; j < 2; j++) {
            const int row = j*32 + r0;
            const float4 qv = *(const float4*)(q + (size_t)row*4096 + n0 + c8);
            *(float4*)&qs[row*QLDKH + c8] = qv;
            const __half2* qh = (const __half2*)&qv;
            #pragma unroll
            for (int p = 0; p < 4; p++) {
                const float2 f = __half22float2(qh[p]);
                ssq[j] += f.x*f.x + f.y*f.y;
            }
            const float4 kv = *(const float4*)(k + (size_t)row*4096 + n0 + c8);
            *(float4*)&ks_[row*QLDKH + c8] = kv;
            const __half2* kh = (const __half2*)&kv;
            #pragma unroll
            for (int p = 0; p < 4; p++) {
                const float2 f = __half22float2(kh[p]);
                ssk[j] += f.x*f.x + f.y*f.y;
            }
        }
        __syncthreads();
        #pragma unroll
        for (int ks = 0; ks < 2; ks++) {
            uint32_t a[4], b[8][2];
            LDM_X4(a[0], a[1], a[2], a[3], aoff + (uint32_t)((ks*16) * 2));
            #pragma unroll
            for (int nt = 0; nt < 8; nt++)
                LDM_X2(b[nt][0], b[nt][1], boff + (uint32_t)((nt*8*QLDKH + ks*16) * 2));
            #pragma unroll
            for (int nt = 0; nt < 8; nt++)
                MMA_F16(acc[nt][0], acc[nt][1], acc[nt][2], acc[nt][3],
                        a[0], a[1], a[2], a[3], b[nt][0], b[nt][1]);
        }
        __syncthreads();
    }
    #pragma unroll
    for (int o = 1; o < 4; o <<= 1) {
        #pragma unroll
        for (int j = 0; j < 2; j++) {
            ssq[j] += __shfl_xor_sync(0xffffffffu, ssq[j], o);
            ssk[j] += __shfl_xor_sync(0xffffffffu, ssk[j], o);
        }
    }
    if ((tid & 3) == 0) {
        #pragma unroll
        for (int j = 0; j < 2; j++) {
            const int row = j*32 + r0;
            g_ss[((size_t)bh*NSPLIT + split)*64 + row]        = ssq[j];
            g_ss[((size_t)(64 + bh)*NSPLIT + split)*64 + row] = ssk[j];
        }
    }
    float* dst = g_Sp + ((size_t)(bh*NSPLIT + split)) * 4096;
    const int g = lane >> 2, tg = lane & 3;
    const int d0 = wid*16 + g;
    #pragma unroll
    for (int nt = 0; nt < 8; nt++) {
        const int e = nt*8 + tg*2;
        float2 v0; v0.x = acc[nt][0]; v0.y = acc[nt][1];
        float2 v1; v1.x = acc[nt][2]; v1.y = acc[nt][3];
        *(float2*)(dst + d0*64 + e)       = v0;
        *(float2*)(dst + (d0 + 8)*64 + e) = v1;
    }
}

// ===========================================================================
// K4b: parallel softmax. grid 64 (bh), 256 thr (8 warps).
// Warp w handles d-rows w*8..w*8+7; each lane owns 2 e-elements.
// ===========================================================================
__global__ void __launch_bounds__(256) softmax_kernel(const float* __restrict__ temperature) {
    __shared__ float scq[64], sck[64];
    const int bh = blockIdx.x;
    const int tid = threadIdx.x;
    const int wid = tid >> 5, lane = tid & 31;
    if (tid < 128) {
        const int iq = tid >> 6;
        const int r = tid & 63;
        float s = 0.0f;
        #pragma unroll
        for (int sp = 0; sp < NSPLIT; sp++)
            s += g_ss[((size_t)(iq*64 + bh)*NSPLIT + sp)*64 + r];
        const float nrm = fmaxf(sqrtf(s), 1e-12f);
        if (iq == 0) scq[r] = temperature[bh & 7] / nrm;
        else         sck[r] = 1.0f / nrm;
    }
    __syncthreads();
    #pragma unroll
    for (int rr = 0; rr < 8; rr++) {
        const int d = wid*8 + rr;
        const int e0 = lane*2;
        float sx = 0.0f, sy = 0.0f;
        #pragma unroll
        for (int sp = 0; sp < NSPLIT; sp++) {
            const float2 v = *(const float2*)&g_Sp[((size_t)(bh*NSPLIT + sp))*4096 + d*64 + e0];
            sx += v.x; sy += v.y;
        }
        const float qsc = scq[d];
        const float v0 = sx * qsc * sck[e0];
        const float v1 = sy * qsc * sck[e0 + 1];
        float mx = fmaxf(v0, v1);
        #pragma unroll
        for (int o = 16; o > 0; o >>= 1) mx = fmaxf(mx, __shfl_xor_sync(0xffffffffu, mx, o));
        const float ex0 = __expf(v0 - mx);
        const float ex1 = __expf(v1 - mx);
        float sm = ex0 + ex1;
        #pragma unroll
        for (int o = 16; o > 0; o >>= 1) sm += __shfl_xor_sync(0xffffffffu, sm, o);
        const float inv = 1.0f / sm;
        *(__half2*)&g_attn[(size_t)bh*4096 + d*64 + e0] = __floats2half2_rn(ex0*inv, ex1*inv);
    }
}

// ===========================================================================
// K4c: fp16 mma attn@v + GELU.
// ===========================================================================
#define ALD 72     // As row stride (halves): attn [d][e]
#define VLD 136    // Vs row stride (halves): v [e][n]
__global__ void __launch_bounds__(256) attn_v_mma() {
    __shared__ __half As[64*ALD];
    __shared__ __half Vs[64*VLD];
    const int bh = blockIdx.x;
    const int b = bh >> 3, h = bh & 7;
    const int n0 = blockIdx.y * 128;
    const __half* __restrict__ v = g_qkv + (size_t)(128 + bh) * 64 * 4096;
    const int tid = threadIdx.x;
    const int wid = tid >> 5, lane = tid & 31;
    const int wm = wid >> 1, wn = wid & 1;
    const uint32_t sa = smem_u32(As), sv = smem_u32(Vs);

    #pragma unroll
    for (int j = 0; j < 2; j++) {
        const int idx = j*256 + tid;
        const int d = idx >> 3;
        const int e8 = (idx & 7) * 8;
        cp16(sa + (d*ALD + e8)*2, g_attn + (size_t)bh*4096 + d*64 + e8);
    }
    #pragma unroll
    for (int j = 0; j < 4; j++) {
        const int idx = j*256 + tid;
        const int e = idx >> 4;
        const int n8 = (idx & 15) * 8;
        cp16(sv + (e*VLD + n8)*2, v + (size_t)e*4096 + n0 + n8);
    }
    asm volatile("cp.async.commit_group;" ::: "memory");
    asm volatile("cp.async.wait_group 0;" ::: "memory");
    __syncthreads();

    const uint32_t aoff = sa + (uint32_t)(((wm*16 + (lane & 15))*ALD + ((lane & 16) ? 8 : 0)) * 2);
    const uint32_t boff = sv + (uint32_t)(((lane & 15)*VLD + wn*64) * 2);

    float acc[8][4];
    #pragma unroll
    for (int nt = 0; nt < 8; nt++)
        #pragma unroll
        for (int r = 0; r < 4; r++) acc[nt][r] = 0.0f;

    #pragma unroll
    for (int ks = 0; ks < 4; ks++) {
        uint32_t a[4], bfr[8][2];
        LDM_X4(a[0], a[1], a[2], a[3], aoff + (uint32_t)((ks*16) * 2));
        #pragma unroll
        for (int nt = 0; nt < 8; nt++)
            LDM_X2_T(bfr[nt][0], bfr[nt][1],
                     boff + (uint32_t)((ks*16*VLD + nt*8) * 2));
        #pragma unroll
        for (int nt = 0; nt < 8; nt++)
            MMA_F16(acc[nt][0], acc[nt][1], acc[nt][2], acc[nt][3],
                    a[0], a[1], a[2], a[3], bfr[nt][0], bfr[nt][1]);
    }

    const int g = lane >> 2, tg = lane & 3;
    const int d0 = wm*16 + g;
    #pragma unroll
    for (int nt = 0; nt < 8; nt++) {
        const int n = n0 + wn*64 + nt*8 + tg*2;
        const size_t t0r = (size_t)b*4096 + n;
        #pragma unroll
        for (int r = 0; r < 4; r++) {
            const int d = d0 + (r >> 1)*8;
            const size_t t = t0r + (r & 1);
            const float xg = acc[nt][r];
            g_y[t*512 + h*64 + d] =
                __float2half(0.5f*xg*(1.0f + erff(xg*0.70710678118654752f)));
        }
    }
}

// ===========================================================================
extern "C" void kernel_launch(void* const* d_in, const int* in_sizes, int n_in,
                              void* d_out, int out_size) {
    const float* x           = (const float*)d_in[0];
    const float* ln_g        = (const float*)d_in[1];
    const float* ln_b        = (const float*)d_in[2];
    const float* qkv_w       = (const float*)d_in[3];
    const float* temperature = (const float*)d_in[4];
    const float* proj_w      = (const float*)d_in[5];
    const float* proj_b      = (const float*)d_in[6];
    float* out = (float*)d_out;

    cudaFuncSetAttribute(mmagemm<0>, cudaFuncAttributeMaxDynamicSharedMemorySize, GEMM_SMEM);
    cudaFuncSetAttribute(mmagemm<1>, cudaFuncAttributeMaxDynamicSharedMemorySize, GEMM_SMEM);

    round_w_kernel<<<512, 256>>>(qkv_w, proj_w);
    ln_kernel<<<Tt, 128>>>(x, ln_g, ln_b);
    mmagemm<0><<<dim3(1536/128, Tt/128), 256, GEMM_SMEM>>>(nullptr, nullptr);
    attn_qk_mma<<<dim3(64, NSPLIT), 128>>>();
    softmax_kernel<<<64, 256>>>(temperature);
    attn_v_mma<<<dim3(64, 32), 256>>>();
    mmagemm<1><<<dim3(512/128, Tt/128), 256, GEMM_SMEM>>>(proj_b, out);
}